// round 13
// baseline (speedup 1.0000x reference)
#include <cuda_runtime.h>
#include <cuda_bf16.h>
#include <math.h>
#include <stdint.h>

#define PER_B 1966080
#define SMB 40

__device__ float g_xin[15728640], g_x1[15728640], g_x1n[15728640];
__device__ float g_fa[4194304], g_fb[4194304];
__device__ __nv_bfloat16 g_Sh[33554432], g_Sl[33554432];
__device__ __nv_bfloat16 g_wihh[1048576], g_wihl[1048576], g_whhh[1048576], g_whhl[1048576];
__device__ __nv_bfloat16 g_hh[2097152], g_hl[2097152];
__device__ __nv_bfloat16 g_hh2[2097152], g_hl2[2097152];
__device__ __nv_bfloat16 g_a1h[2097152], g_a1l[2097152], g_aTh[2097152], g_aTl[2097152];
__device__ __nv_bfloat16 g_chh[2097152], g_chl[2097152];
__device__ __nv_bfloat16 g_x1th[15728640], g_x1tl[15728640];
__device__ __nv_bfloat16 g_colh[141557760], g_coll[141557760];
__device__ __nv_bfloat16 g_gwh[73728], g_gwl[73728];
__device__ float g_bias[2048];
__device__ float g_G0[134217728];
__device__ float g_h[2097152], g_c[2097152];
__device__ float g_P[2097152];
__device__ float g_xg[31457280];
__device__ float g_cv[31457280];
__device__ float g_x1b[15728640];
__device__ float g_tf1[245760], g_tf2[30720];
__device__ float g_lg2[28800];
__device__ float g_sc[60], g_sh[60];
__device__ float g_Tc[28800];
__device__ float g_y[15728640];
__device__ double g_part[8192];
__device__ float g_mu[8], g_inv[8];

__device__ __forceinline__ float sg(float x){ return 1.f/(1.f+__expf(-x)); }
__device__ __forceinline__ float lr(float x){ return x>0.f?x:0.01f*x; }
__device__ __forceinline__ void bsplit(float v, __nv_bfloat16* H, __nv_bfloat16* L, long o){
    __nv_bfloat16 h = __float2bfloat16(v);
    H[o]=h; L[o]=__float2bfloat16(v-__bfloat162float(h));
}
__device__ __forceinline__ uint32_t smem_u32(const void* p){
    uint32_t a; asm("{ .reg .u64 t; cvta.to.shared.u64 t, %1; cvt.u32.u64 %0, t; }" : "=r"(a) : "l"(p)); return a;
}
#define LDSM4(r,addr) asm volatile("ldmatrix.sync.aligned.m8n8.x4.shared.b16 {%0,%1,%2,%3}, [%4];" \
  : "=r"((r)[0]),"=r"((r)[1]),"=r"((r)[2]),"=r"((r)[3]) : "r"(addr))
#define MMA(c,a,b0,b1) asm volatile("mma.sync.aligned.m16n8k16.row.col.f32.bf16.bf16.f32 " \
  "{%0,%1,%2,%3},{%4,%5,%6,%7},{%8,%9},{%0,%1,%2,%3};" \
  : "+f"((c)[0]),"+f"((c)[1]),"+f"((c)[2]),"+f"((c)[3]) \
  : "r"((a)[0]),"r"((a)[1]),"r"((a)[2]),"r"((a)[3]),"r"(b0),"r"(b1))
#define CPA(d,s) asm volatile("cp.async.cg.shared.global [%0],[%1],16;" :: "r"(d),"l"(s))
#define CPC()    asm volatile("cp.async.commit_group;" ::: "memory")
#define CPW0()   asm volatile("cp.async.wait_group 0;" ::: "memory")
#define CPW1()   asm volatile("cp.async.wait_group 1;" ::: "memory")

#define TG_MAINLOOP(Ah,Al,Bh,Bl,Kd) \
    auto ldst = [&](int st, int k0){ \
        __nv_bfloat16* S = smp + st*20480; \
        for(int i=tid;i<512;i+=256){ \
            int r=i>>2, u=i&3; \
            uint32_t d = smem_u32(&S[r*SMB+u*8]); \
            CPA(d,       Ah+(bm+r)*Kd+k0+u*8); \
            CPA(d+10240, Al+(bm+r)*Kd+k0+u*8); \
            CPA(d+20480, Bh+(bn+r)*Kd+k0+u*8); \
            CPA(d+30720, Bl+(bn+r)*Kd+k0+u*8); \
        } \
    }; \
    int nc = (Kd)>>5; \
    ldst(0,0); CPC(); \
    for(int c=0;c<nc;c++){ \
        int cur = c&1; \
        if(c+1<nc){ ldst(cur^1,(c+1)<<5); CPC(); CPW1(); } \
        else CPW0(); \
        __syncthreads(); \
        __nv_bfloat16* S = smp + cur*20480; \
        const __nv_bfloat16 *A0=S, *A1=S+5120, *B0=S+10240, *B1=S+15360; \
        _Pragma("unroll") \
        for(int ks=0;ks<2;ks++){ \
            uint32_t ah[2][4], al[2][4]; \
            int arow = wm + (lane&15), acol = ks*16 + (lane>>4)*8; \
            _Pragma("unroll") \
            for(int mi=0;mi<2;mi++){ \
                LDSM4(ah[mi], smem_u32(&A0[(arow+mi*16)*SMB+acol])); \
                LDSM4(al[mi], smem_u32(&A1[(arow+mi*16)*SMB+acol])); \
            } \
            _Pragma("unroll") \
            for(int g=0;g<4;g++){ \
                uint32_t bh[4], bl[4]; \
                int nrow = wn + g*16 + ((lane>>4)*8) + (lane&7); \
                int bcol = ks*16 + ((lane>>3)&1)*8; \
                LDSM4(bh, smem_u32(&B0[nrow*SMB+bcol])); \
                LDSM4(bl, smem_u32(&B1[nrow*SMB+bcol])); \
                _Pragma("unroll") \
                for(int mi=0;mi<2;mi++){ \
                    MMA(acc[mi][g*2],   ah[mi], bh[0], bh[1]); \
                    MMA(acc[mi][g*2+1], ah[mi], bh[2], bh[3]); \
                    MMA(acc[mi][g*2],   al[mi], bh[0], bh[1]); \
                    MMA(acc[mi][g*2+1], al[mi], bh[2], bh[3]); \
                    MMA(acc[mi][g*2],   ah[mi], bl[0], bl[1]); \
                    MMA(acc[mi][g*2+1], ah[mi], bl[2], bl[3]); \
                } \
            } \
        } \
        __syncthreads(); \
    }

__global__ __launch_bounds__(256) void tgemm(
    const __nv_bfloat16* __restrict__ Ah, const __nv_bfloat16* __restrict__ Al,
    const __nv_bfloat16* __restrict__ Bh, const __nv_bfloat16* __restrict__ Bl,
    float* __restrict__ C, int N, int K, long sA, long sB, long sC)
{
    extern __shared__ __nv_bfloat16 smp[];
    Ah += (long)blockIdx.z*sA; Al += (long)blockIdx.z*sA;
    Bh += (long)blockIdx.z*sB; Bl += (long)blockIdx.z*sB;
    C  += (long)blockIdx.z*sC;
    int tid = threadIdx.x, lane = tid&31, w = tid>>5;
    long bm = (long)blockIdx.y*128, bn = (long)blockIdx.x*128;
    int wm = (w&3)*32, wn = (w>>2)*64;
    float acc[2][8][4];
    #pragma unroll
    for(int i=0;i<2;i++)
      #pragma unroll
      for(int j=0;j<8;j++)
        #pragma unroll
        for(int k=0;k<4;k++) acc[i][j][k]=0.f;
    TG_MAINLOOP(Ah,Al,Bh,Bl,K)
    #pragma unroll
    for(int mi=0;mi<2;mi++)
      #pragma unroll
      for(int ni=0;ni<8;ni++){
        long rg = bm + wm + mi*16 + (lane>>2);
        long cg = bn + wn + ni*8 + (lane&3)*2;
        *(float2*)&C[rg*N+cg]     = make_float2(acc[mi][ni][0], acc[mi][ni][1]);
        *(float2*)&C[(rg+8)*N+cg] = make_float2(acc[mi][ni][2], acc[mi][ni][3]);
      }
}

// fused recurrent step, ping-pong h buffers (read Ah/Al, write Wh/Wl).
__global__ __launch_bounds__(256) void tlstm(
    const __nv_bfloat16* __restrict__ Ah, const __nv_bfloat16* __restrict__ Al,
    const __nv_bfloat16* __restrict__ Bh, const __nv_bfloat16* __restrict__ Bl,
    __nv_bfloat16* __restrict__ Wh, __nv_bfloat16* __restrict__ Wl, int t)
{
    extern __shared__ __nv_bfloat16 smp[];
    int tid = threadIdx.x, lane = tid&31, w = tid>>5;
    long bm = (long)blockIdx.y*128, bn = (long)blockIdx.x*128;
    int wm = (w&3)*32, wn = (w>>2)*64;
    float acc[2][8][4];
    #pragma unroll
    for(int i=0;i<2;i++)
      #pragma unroll
      for(int j=0;j<8;j++)
        #pragma unroll
        for(int k=0;k<4;k++) acc[i][j][k]=0.f;
    TG_MAINLOOP(Ah,Al,Bh,Bl,512)
    long tOff = (long)t*4096;
    #pragma unroll
    for(int mi=0;mi<2;mi++)
      #pragma unroll
      for(int ni=0;ni<8;ni++){
        int lcol = wn + ni*8 + (lane&3)*2;
        long gcol = bn + lcol;
        long r0 = bm + wm + mi*16 + (lane>>2);
        float b0 = g_bias[gcol], b1 = g_bias[gcol+1];
        float p00 = acc[mi][ni][0] + g_G0[(tOff+r0)*2048+gcol]     + b0;
        float p01 = acc[mi][ni][1] + g_G0[(tOff+r0)*2048+gcol+1]   + b1;
        float p10 = acc[mi][ni][2] + g_G0[(tOff+r0+8)*2048+gcol]   + b0;
        float p11 = acc[mi][ni][3] + g_G0[(tOff+r0+8)*2048+gcol+1] + b1;
        float q00 = __shfl_xor_sync(0xffffffffu,p00,1);
        float q01 = __shfl_xor_sync(0xffffffffu,p01,1);
        float q10 = __shfl_xor_sync(0xffffffffu,p10,1);
        float q11 = __shfl_xor_sync(0xffffffffu,p11,1);
        if((lane&1)==0){
            long u = gcol>>2;
            {
                float iv=sg(p00), fv=sg(p01), gv=tanhf(q00), ov=sg(q01);
                long idx=r0*512+u;
                float cc=fv*g_c[idx]+iv*gv; g_c[idx]=cc;
                float h=ov*tanhf(cc); g_h[idx]=h; bsplit(h,Wh,Wl,idx);
            }
            {
                float iv=sg(p10), fv=sg(p11), gv=tanhf(q10), ov=sg(q11);
                long idx=(r0+8)*512+u;
                float cc=fv*g_c[idx]+iv*gv; g_c[idx]=cc;
                float h=ov*tanhf(cc); g_h[idx]=h; bsplit(h,Wh,Wl,idx);
            }
        }
      }
}

__global__ void k_prep(){
    int i = blockIdx.x*256+threadIdx.x;
    if(i<2097152){ g_c[i]=0.f; g_hh[i]=__float2bfloat16(0.f); g_hl[i]=__float2bfloat16(0.f); }
}
__global__ void k_wsplit(const float* __restrict__ wih, const float* __restrict__ whh,
                         const float* __restrict__ gw, const float* __restrict__ bih,
                         const float* __restrict__ bhh){
    int i = blockIdx.x*256+threadIdx.x;
    if(i<1048576){
        int j = i>>9, k = i&511;
        int u = j>>2, gate = j&3;
        int src = (gate*512+u)*512 + k;
        bsplit(wih[src],g_wihh,g_wihl,i);
        bsplit(whh[src],g_whhh,g_whhl,i);
    }
    if(i<73728) bsplit(gw[i],g_gwh,g_gwl,i);
    if(i<2048){ int u=i>>2, gate=i&3; g_bias[i]=bih[gate*512+u]+bhh[gate*512+u]; }
}

__global__ __launch_bounds__(256) void k_conv1(const float* __restrict__ x, const float* __restrict__ w1,
    const float* __restrict__ b1, const float* __restrict__ wt, const float* __restrict__ bt)
{
    int b = blockIdx.x>>9, n = blockIdx.x&511, tid = threadIdx.x;
    __shared__ float xs[16][60]; __shared__ float sw1[1024]; __shared__ float swt[3072];
    __shared__ float sb1[64], sbt[64];
    for(int i=tid;i<960;i+=256) xs[i/60][i%60] = x[((b*16 + i/60)*512 + n)*60 + i%60];
    for(int i=tid;i<1024;i+=256) sw1[i]=w1[i];
    for(int i=tid;i<3072;i+=256) swt[i]=wt[i];
    if(tid<64){ sb1[tid]=b1[tid]; sbt[tid]=bt[tid]; }
    __syncthreads();
    for(int i=tid;i<3840;i+=256){
        int co=i/60, l=i%60;
        float a1=sb1[co], a2=sbt[co];
        #pragma unroll
        for(int ci=0;ci<16;ci++){
            float xv=xs[ci][l];
            a1 = fmaf(sw1[co*16+ci],xv,a1);
            const float* w=&swt[(co*16+ci)*3];
            if(l>0) a2 = fmaf(w[0],xs[ci][l-1],a2);
            a2 = fmaf(w[1],xv,a2);
            if(l<59) a2 = fmaf(w[2],xs[ci][l+1],a2);
        }
        int o = ((b*64+co)*512+n)*60+l;
        g_xin[o]=a1;
        float v=lr(a2);
        g_x1[o]=v;
        g_x1n[((b*512+n)*64+co)*60+l]=v;
    }
}

__global__ __launch_bounds__(256) void k_x1t(){
    int bc = blockIdx.x, nch = blockIdx.y, tid = threadIdx.x;
    __shared__ float t[64][61];
    for(int i=tid;i<3840;i+=256){
        int n=i/60, l=i%60;
        t[n][l] = g_x1[((long)bc*512 + nch*64 + n)*60 + l];
    }
    __syncthreads();
    int b = bc>>6, c = bc&63;
    for(int i=tid;i<3840;i+=256){
        int l=i>>6, n=i&63;
        if(l<60){
            long o = ((long)b*3840 + c*60 + l)*512 + nch*64 + n;
            bsplit(t[n][l], g_x1th, g_x1tl, o);
        }
    }
}

__global__ __launch_bounds__(256) void k_feat(const float* __restrict__ w31, const float* __restrict__ w32,
    const float* __restrict__ w21, const float* __restrict__ w22)
{
    int b = blockIdx.x>>9, n = blockIdx.x&511, tid = threadIdx.x;
    __shared__ float xs[64][60];
    for(int i=tid;i<3840;i+=256) xs[i/60][i%60] = g_x1[((b*64+i/60)*512+n)*60 + i%60];
    __syncthreads();
    for(int it=tid; it<512; it+=256){
        int wsel = it>>8, rem = it&255, co = rem>>2, t2 = rem&3;
        const float* W = wsel ? w32 : w31;
        float a=0.f;
        for(int c=0;c<64;c++){
            const float* wr = &W[co*768 + c*12];
            #pragma unroll
            for(int t1=0;t1<12;t1++) a = fmaf(wr[t1],xs[c][t1*4+t2],a);
        }
        float* dst = wsel ? g_fb : g_fa;
        dst[((b*16+t2)*512+n)*64+co] = a;
    }
    for(int it=tid; it<1536; it+=256){
        int wsel = it/768, rem = it%768, co = rem/12, tt = rem%12;
        const float* W = wsel ? w22 : w21;
        float a=0.f;
        #pragma unroll 8
        for(int c=0;c<64;c++) a = fmaf(W[co*64+c],xs[c][48+tt],a);
        float* dst = wsel ? g_fb : g_fa;
        dst[((b*16+4+tt)*512+n)*64+co] = a;
    }
}

__global__ __launch_bounds__(256) void k_slog(){
    int b = blockIdx.z>>4, t = blockIdx.z&15;
    int n0 = blockIdx.y*64, q0 = blockIdx.x*64, tid=threadIdx.x;
    __shared__ float As[64][65], Bs[64][65];
    const float* fa = &g_fa[((b*16+t)*512+n0)*64];
    const float* fb = &g_fb[((b*16+t)*512+q0)*64];
    for(int i=tid;i<4096;i+=256){ As[i>>6][i&63]=fa[i]; Bs[i>>6][i&63]=fb[i]; }
    __syncthreads();
    int tn = (tid>>4)*4, tq = (tid&15)*4;
    float acc[4][4][4];
    #pragma unroll
    for(int i=0;i<4;i++)
      #pragma unroll
      for(int j=0;j<4;j++)
        #pragma unroll
        for(int m=0;m<4;m++) acc[i][j][m]=0.f;
    for(int co=0;co<64;co+=4){
        #pragma unroll
        for(int m=0;m<4;m++){
            float a[4],bb[4];
            #pragma unroll
            for(int i=0;i<4;i++) a[i]=As[tn+i][co+m];
            #pragma unroll
            for(int j=0;j<4;j++) bb[j]=Bs[tq+j][co+m];
            #pragma unroll
            for(int i=0;i<4;i++)
              #pragma unroll
              for(int j=0;j<4;j++) acc[i][j][m]=fmaf(a[i],bb[j],acc[i][j][m]);
        }
    }
    #pragma unroll
    for(int i=0;i<4;i++)
      #pragma unroll
      for(int j=0;j<4;j++){
        float s = 0.25f*(sg(acc[i][j][0])+sg(acc[i][j][1])+sg(acc[i][j][2])+sg(acc[i][j][3]));
        long o = (long)(t*4096 + b*512 + n0+tn+i)*512 + q0+tq+j;
        bsplit(s, g_Sh, g_Sl, o);
    }
}

__global__ void k_adj1(const float* __restrict__ sup){
    int i = blockIdx.x*256+threadIdx.x;
    if(i>=2097152) return;
    float v = g_h[i]*sup[i];
    bsplit(v, g_a1h, g_a1l, i);
    int b = i>>18, r = i&262143;
    int q = r>>9, n = r&511;
    long oT = ((long)b<<18) + ((long)n<<9) + q;
    bsplit(v, g_aTh, g_aTl, oT);
}

__global__ void k_cheb(){
    int i = blockIdx.x*256+threadIdx.x;
    if(i>=2097152) return;
    int q = (i>>9)&511, nn = i&511;
    float v = 2.f*g_P[i] - (q==nn?1.f:0.f);
    bsplit(v, g_chh, g_chl, i);
}

__global__ void k_im2col(){
    long idx = (long)blockIdx.x*256+threadIdx.x;
    if(idx>=141557760L) return;
    int k = (int)(idx%576);
    long rg = idx/576;
    int row = (int)(rg%30720), b = (int)(rg/30720);
    int cc = k/3, j = k%3, c = cc/3, kd = cc%3;
    int q = row/60, l = row%60, li = l+j-1;
    float v=0.f;
    if(li>=0 && li<60){
        if(kd==0) v = g_x1n[((b*512+q)*64+c)*60+li];
        else      v = g_xg[((long)(b*2+kd-1)*512+q)*3840 + c*60+li];
    }
    bsplit(v, g_colh, g_coll, idx);
}

__global__ void k_comb(const float* __restrict__ gb_){
    int idx = blockIdx.x*256+threadIdx.x;
    if(idx>=15728640) return;
    int l = idx%60, n = (idx/60)&511, c = (idx/30720)&63, b = idx/PER_B;
    float f = g_cv[(long)(b*128+c)*30720 + n*60+l] + gb_[c];
    float g = g_cv[(long)(b*128+c+64)*30720 + n*60+l] + gb_[c+64];
    g_x1b[idx] = sg(g)*lr(f);
}

__global__ __launch_bounds__(256) void k_tf1(const float* __restrict__ w){
    int b = blockIdx.x>>9, n = blockIdx.x&511, tid = threadIdx.x;
    __shared__ float xs[64][60]; __shared__ float ws[64];
    for(int i=tid;i<3840;i+=256) xs[i/60][i%60] = g_x1b[((b*64+i/60)*512+n)*60+i%60];
    if(tid<64) ws[tid]=w[tid];
    __syncthreads();
    if(tid<60){
        float a=0.f;
        #pragma unroll 8
        for(int c=0;c<64;c++) a = fmaf(ws[c],xs[c][tid],a);
        g_tf1[(b*60+tid)*512+n]=a;
    }
}

__global__ void k_tf2(const float* __restrict__ w){
    int idx = blockIdx.x*256+threadIdx.x;
    if(idx>=30720) return;
    int l = idx%60, c = (idx/60)&63, b = idx/3840;
    const float* xp = &g_x1b[((long)(b*64+c)*512)*60 + l];
    float a=0.f;
    for(int n=0;n<512;n++) a = fmaf(w[n],xp[n*60],a);
    g_tf2[idx]=a;
}

__global__ __launch_bounds__(256) void k_tatt(const float* __restrict__ tw,
        const float* __restrict__ tb, const float* __restrict__ tv){
    int b = blockIdx.x, tid = threadIdx.x;
    __shared__ float tmp[60][64], f2s[64][60], lgs[60][60];
    for(int i=tid;i<3840;i+=256) f2s[i/60][i%60] = g_tf2[b*3840+i];
    for(int i=tid;i<3840;i+=256){
        int l=i>>6, c=i&63;
        const float* f1 = &g_tf1[(b*60+l)*512];
        float a=0.f;
        for(int n=0;n<512;n++) a = fmaf(f1[n],tw[n*64+c],a);
        tmp[l][c]=a;
    }
    __syncthreads();
    for(int i=tid;i<3600;i+=256){
        int l=i/60, q=i%60;
        float a=tb[l*60+q];
        #pragma unroll
        for(int c=0;c<64;c++) a = fmaf(tmp[l][c],f2s[c][q],a);
        lgs[l][q]=sg(a);
    }
    __syncthreads();
    for(int i=tid;i<3600;i+=256){
        int ii=i/60, t=i%60;
        float a=0.f;
        #pragma unroll 10
        for(int q=0;q<60;q++) a = fmaf(tv[ii*60+q],lgs[q][t],a);
        g_lg2[b*3600+i]=a;
    }
}

__global__ void k_bn1(const float* __restrict__ gam, const float* __restrict__ bet){
    int t = threadIdx.x;
    if(t>=60) return;
    double s=0, s2=0;
    for(int b=0;b<8;b++)
        for(int i=0;i<60;i++){
            double v = (double)g_lg2[b*3600+i*60+t]; s+=v; s2+=v*v;
        }
    double mu=s/480.0, var=s2/480.0-mu*mu;
    float scv = gam[t]*rsqrtf((float)var+1e-5f);
    g_sc[t]=scv; g_sh[t]=bet[t]-(float)mu*scv;
}

__device__ __forceinline__ int blk4(int i){ return i<12?0:(i<24?1:(i<36?2:3)); }

__global__ void k_bn2(){
    int row = blockIdx.x;
    int b = row/60, i = row%60, tid=threadIdx.x;
    __shared__ float v[60];
    if(tid<60){
        float x = g_lg2[b*3600+i*60+tid]*g_sc[tid]+g_sh[tid];
        if(blk4(i)!=blk4(tid)) x = -1e13f;
        v[tid]=x;
    }
    __syncthreads();
    if(tid==0){
        float m=-1e30f;
        for(int t=0;t<60;t++) m=fmaxf(m,v[t]);
        float s=0.f;
        for(int t=0;t<60;t++){ float e=__expf(v[t]-m); v[t]=e; s+=e; }
        float inv=1.f/s;
        for(int t=0;t<60;t++) g_Tc[b*3600+i*60+t]=v[t]*inv;
    }
}

__global__ __launch_bounds__(256) void k_x2(){
    int b = blockIdx.x>>9, n = blockIdx.x&511, tid=threadIdx.x;
    __shared__ float Tcs[60][60], xs[64][60];
    __shared__ double rs[256], rs2[256];
    for(int i=tid;i<3600;i+=256) Tcs[i/60][i%60]=g_Tc[b*3600+i];
    for(int i=tid;i<3840;i+=256) xs[i/60][i%60]=g_x1b[((b*64+i/60)*512+n)*60+i%60];
    __syncthreads();
    double ls=0, ls2=0;
    for(int i=tid;i<3840;i+=256){
        int c=i/60, q=i%60;
        float a=0.f;
        #pragma unroll
        for(int l=0;l<60;l++) a = fmaf(xs[c][l],Tcs[q][l],a);
        int o = ((b*64+c)*512+n)*60+q;
        float y = lr(a)+g_xin[o];
        g_y[o]=y;
        ls += (double)y; ls2 += (double)y*(double)y;
    }
    rs[tid]=ls; rs2[tid]=ls2;
    __syncthreads();
    for(int s=128;s>0;s>>=1){
        if(tid<s){ rs[tid]+=rs[tid+s]; rs2[tid]+=rs2[tid+s]; }
        __syncthreads();
    }
    if(tid==0){ g_part[blockIdx.x*2]=rs[0]; g_part[blockIdx.x*2+1]=rs2[0]; }
}

__global__ void k_lnred(){
    int b = blockIdx.x, tid = threadIdx.x;
    __shared__ double rs[256], rs2[256];
    rs[tid]  = g_part[(b*512+tid)*2]   + g_part[(b*512+tid+256)*2];
    rs2[tid] = g_part[(b*512+tid)*2+1] + g_part[(b*512+tid+256)*2+1];
    __syncthreads();
    for(int k=128;k>0;k>>=1){
        if(tid<k){ rs[tid]+=rs[tid+k]; rs2[tid]+=rs2[tid+k]; }
        __syncthreads();
    }
    if(tid==0){
        double mu = rs[0]/1966080.0, var = rs2[0]/1966080.0 - mu*mu;
        g_mu[b]=(float)mu; g_inv[b]=(float)(1.0/sqrt(var+1e-5));
    }
}

__global__ void k_lnout(const float* __restrict__ lg_, const float* __restrict__ lb_, float* __restrict__ out){
    int idx = blockIdx.x*256+threadIdx.x;
    if(idx>=15728640) return;
    int b = idx/PER_B, i = idx%PER_B;
    out[idx] = (g_y[idx]-g_mu[b])*g_inv[b]*lg_[i]+lb_[i];
}

__global__ void k_tail(float* __restrict__ out){
    int idx = blockIdx.x*256+threadIdx.x;
    if(idx<2097152) out[15728640+idx]=g_h[idx];
    else if(idx<2125952) out[15728640+idx]=g_Tc[idx-2097152];
}

extern "C" void kernel_launch(void* const* d_in, const int* in_sizes, int n_in,
                              void* d_out, int out_size) {
    const float* x       =(const float*)d_in[0];
    const float* supports=(const float*)d_in[1];
    const float* conv1_w =(const float*)d_in[2];
    const float* conv1_b =(const float*)d_in[3];
    const float* tconv_w =(const float*)d_in[4];
    const float* tconv_b =(const float*)d_in[5];
    const float* s3_w1   =(const float*)d_in[6];
    const float* s3_w2   =(const float*)d_in[7];
    const float* s2_w1   =(const float*)d_in[8];
    const float* s2_w2   =(const float*)d_in[9];
    const float* wih     =(const float*)d_in[10];
    const float* whh     =(const float*)d_in[11];
    const float* bih     =(const float*)d_in[12];
    const float* bhh     =(const float*)d_in[13];
    const float* gcn_w   =(const float*)d_in[14];
    const float* gcn_b   =(const float*)d_in[15];
    const float* t_w1    =(const float*)d_in[16];
    const float* t_w2    =(const float*)d_in[17];
    const float* t_w     =(const float*)d_in[18];
    const float* t_b     =(const float*)d_in[19];
    const float* t_v     =(const float*)d_in[20];
    const float* t_bn_g  =(const float*)d_in[21];
    const float* t_bn_b  =(const float*)d_in[22];
    const float* ln_g    =(const float*)d_in[23];
    const float* ln_b    =(const float*)d_in[24];
    float* out=(float*)d_out;

    float *pG0,*pP,*pxg,*pcv;
    __nv_bfloat16 *pSh,*pSl,*pwihh,*pwihl,*pwhhh,*pwhhl,*phh,*phl,*phh2,*phl2;
    __nv_bfloat16 *pa1h,*pa1l,*paTh,*paTl,*pchh,*pchl,*px1th,*px1tl,*pcolh,*pcoll,*pgwh,*pgwl;
    cudaGetSymbolAddress((void**)&pG0,  g_G0);
    cudaGetSymbolAddress((void**)&pP,   g_P);
    cudaGetSymbolAddress((void**)&pxg,  g_xg);
    cudaGetSymbolAddress((void**)&pcv,  g_cv);
    cudaGetSymbolAddress((void**)&pSh,  g_Sh);
    cudaGetSymbolAddress((void**)&pSl,  g_Sl);
    cudaGetSymbolAddress((void**)&pwihh,g_wihh);
    cudaGetSymbolAddress((void**)&pwihl,g_wihl);
    cudaGetSymbolAddress((void**)&pwhhh,g_whhh);
    cudaGetSymbolAddress((void**)&pwhhl,g_whhl);
    cudaGetSymbolAddress((void**)&phh,  g_hh);
    cudaGetSymbolAddress((void**)&phl,  g_hl);
    cudaGetSymbolAddress((void**)&phh2, g_hh2);
    cudaGetSymbolAddress((void**)&phl2, g_hl2);
    cudaGetSymbolAddress((void**)&pa1h, g_a1h);
    cudaGetSymbolAddress((void**)&pa1l, g_a1l);
    cudaGetSymbolAddress((void**)&paTh, g_aTh);
    cudaGetSymbolAddress((void**)&paTl, g_aTl);
    cudaGetSymbolAddress((void**)&pchh, g_chh);
    cudaGetSymbolAddress((void**)&pchl, g_chl);
    cudaGetSymbolAddress((void**)&px1th,g_x1th);
    cudaGetSymbolAddress((void**)&px1tl,g_x1tl);
    cudaGetSymbolAddress((void**)&pcolh,g_colh);
    cudaGetSymbolAddress((void**)&pcoll,g_coll);
    cudaGetSymbolAddress((void**)&pgwh, g_gwh);
    cudaGetSymbolAddress((void**)&pgwl, g_gwl);

    cudaFuncSetAttribute(tgemm, cudaFuncAttributeMaxDynamicSharedMemorySize, 81920);
    cudaFuncSetAttribute(tlstm, cudaFuncAttributeMaxDynamicSharedMemorySize, 81920);
    const int TS = 81920;

    k_prep<<<8192,256>>>();
    k_wsplit<<<4096,256>>>(wih, whh, gcn_w, bih, bhh);
    k_conv1<<<4096,256>>>(x, conv1_w, conv1_b, tconv_w, tconv_b);
    k_x1t<<<dim3(512,8),256>>>();
    k_feat<<<4096,256>>>(s3_w1,s3_w2,s2_w1,s2_w2);
    k_slog<<<dim3(8,8,128),256>>>();
    tgemm<<<dim3(16,512,1),256,TS>>>(pSh,pSl,pwihh,pwihl,pG0,2048,512,0,0,0);
    for(int t=0;t<16;t++){
        __nv_bfloat16 *rh = (t&1)? phh2 : phh,  *rl = (t&1)? phl2 : phl;
        __nv_bfloat16 *wh = (t&1)? phh  : phh2, *wl = (t&1)? phl  : phl2;
        tlstm<<<dim3(16,32),256,TS>>>(rh,rl,pwhhh,pwhhl,wh,wl,t);
    }
    k_adj1<<<8192,256>>>(supports);
    tgemm<<<dim3(4,4,8),256,TS>>>(pa1h,pa1l,paTh,paTl,pP,512,512,262144,262144,262144);
    k_cheb<<<8192,256>>>();
    tgemm<<<dim3(30,4,8),256,TS>>>(pa1h,pa1l,px1th,px1tl,pxg,        3840,512,262144,1966080,3932160);
    tgemm<<<dim3(30,4,8),256,TS>>>(pchh,pchl,px1th,px1tl,pxg+1966080,3840,512,262144,1966080,3932160);
    k_im2col<<<552960,256>>>();
    tgemm<<<dim3(240,1,8),256,TS>>>(pgwh,pgwl,pcolh,pcoll,pcv,30720,576,0,17694720,3932160);
    k_comb<<<61440,256>>>(gcn_b);
    k_tf1<<<4096,256>>>(t_w1);
    k_tf2<<<120,256>>>(t_w2);
    k_tatt<<<8,256>>>(t_w,t_b,t_v);
    k_bn1<<<1,64>>>(t_bn_g,t_bn_b);
    k_bn2<<<480,64>>>();
    k_x2<<<4096,256>>>();
    k_lnred<<<8,256>>>();
    k_lnout<<<61440,256>>>(ln_g,ln_b,out);
    if(out_size >= 17854592) k_tail<<<8306,256>>>(out);
}

// round 14
// speedup vs baseline: 1.0043x; 1.0043x over previous
#include <cuda_runtime.h>
#include <cuda_bf16.h>
#include <math.h>
#include <stdint.h>

#define PER_B 1966080
#define SMB 40

__device__ float g_xin[15728640], g_x1[15728640], g_x1n[15728640];
__device__ float g_fa[4194304], g_fb[4194304];
__device__ __nv_bfloat16 g_Sh[33554432], g_Sl[33554432];
__device__ __nv_bfloat16 g_wihh[1048576], g_wihl[1048576], g_whhh[1048576], g_whhl[1048576];
__device__ __nv_bfloat16 g_hh[2097152], g_hl[2097152];
__device__ __nv_bfloat16 g_hh2[2097152], g_hl2[2097152];
__device__ __nv_bfloat16 g_a1h[2097152], g_a1l[2097152], g_aTh[2097152], g_aTl[2097152];
__device__ __nv_bfloat16 g_chh[2097152], g_chl[2097152];
__device__ __nv_bfloat16 g_x1th[15728640], g_x1tl[15728640];
__device__ __nv_bfloat16 g_colh[141557760], g_coll[141557760];
__device__ __nv_bfloat16 g_gwh[73728], g_gwl[73728];
__device__ float g_bias[2048];
__device__ float g_G0[134217728];
__device__ float g_h[2097152], g_c[2097152];
__device__ float g_P[2097152];
__device__ float g_xg[31457280];
__device__ float g_cv[31457280];
__device__ float g_x1b[15728640];
__device__ float g_tf1[245760], g_tf2[30720];
__device__ float g_lg2[28800];
__device__ float g_sc[60], g_sh[60];
__device__ float g_Tc[28800];
__device__ float g_y[15728640];
__device__ double g_part[8192];
__device__ float g_mu[8], g_inv[8];

__device__ __forceinline__ float sg(float x){ return 1.f/(1.f+__expf(-x)); }
__device__ __forceinline__ float lr(float x){ return x>0.f?x:0.01f*x; }
__device__ __forceinline__ void bsplit(float v, __nv_bfloat16* H, __nv_bfloat16* L, long o){
    __nv_bfloat16 h = __float2bfloat16(v);
    H[o]=h; L[o]=__float2bfloat16(v-__bfloat162float(h));
}
__device__ __forceinline__ uint32_t smem_u32(const void* p){
    uint32_t a; asm("{ .reg .u64 t; cvta.to.shared.u64 t, %1; cvt.u32.u64 %0, t; }" : "=r"(a) : "l"(p)); return a;
}
#define LDSM4(r,addr) asm volatile("ldmatrix.sync.aligned.m8n8.x4.shared.b16 {%0,%1,%2,%3}, [%4];" \
  : "=r"((r)[0]),"=r"((r)[1]),"=r"((r)[2]),"=r"((r)[3]) : "r"(addr))
#define MMA(c,a,b0,b1) asm volatile("mma.sync.aligned.m16n8k16.row.col.f32.bf16.bf16.f32 " \
  "{%0,%1,%2,%3},{%4,%5,%6,%7},{%8,%9},{%0,%1,%2,%3};" \
  : "+f"((c)[0]),"+f"((c)[1]),"+f"((c)[2]),"+f"((c)[3]) \
  : "r"((a)[0]),"r"((a)[1]),"r"((a)[2]),"r"((a)[3]),"r"(b0),"r"(b1))
#define CPA(d,s) asm volatile("cp.async.cg.shared.global [%0],[%1],16;" :: "r"(d),"l"(s))
#define CPC()    asm volatile("cp.async.commit_group;" ::: "memory")
#define CPW0()   asm volatile("cp.async.wait_group 0;" ::: "memory")
#define CPW1()   asm volatile("cp.async.wait_group 1;" ::: "memory")

#define TG_MAINLOOP(Ah,Al,Bh,Bl,Kd) \
    auto ldst = [&](int st, int k0){ \
        __nv_bfloat16* S = smp + st*20480; \
        for(int i=tid;i<512;i+=256){ \
            int r=i>>2, u=i&3; \
            uint32_t d = smem_u32(&S[r*SMB+u*8]); \
            CPA(d,       Ah+(bm+r)*Kd+k0+u*8); \
            CPA(d+10240, Al+(bm+r)*Kd+k0+u*8); \
            CPA(d+20480, Bh+(bn+r)*Kd+k0+u*8); \
            CPA(d+30720, Bl+(bn+r)*Kd+k0+u*8); \
        } \
    }; \
    int nc = (Kd)>>5; \
    ldst(0,0); CPC(); \
    for(int c=0;c<nc;c++){ \
        int cur = c&1; \
        if(c+1<nc){ ldst(cur^1,(c+1)<<5); CPC(); CPW1(); } \
        else CPW0(); \
        __syncthreads(); \
        __nv_bfloat16* S = smp + cur*20480; \
        const __nv_bfloat16 *A0=S, *A1=S+5120, *B0=S+10240, *B1=S+15360; \
        _Pragma("unroll") \
        for(int ks=0;ks<2;ks++){ \
            uint32_t ah[2][4], al[2][4]; \
            int arow = wm + (lane&15), acol = ks*16 + (lane>>4)*8; \
            _Pragma("unroll") \
            for(int mi=0;mi<2;mi++){ \
                LDSM4(ah[mi], smem_u32(&A0[(arow+mi*16)*SMB+acol])); \
                LDSM4(al[mi], smem_u32(&A1[(arow+mi*16)*SMB+acol])); \
            } \
            _Pragma("unroll") \
            for(int g=0;g<4;g++){ \
                uint32_t bh[4], bl[4]; \
                int nrow = wn + g*16 + ((lane>>4)*8) + (lane&7); \
                int bcol = ks*16 + ((lane>>3)&1)*8; \
                LDSM4(bh, smem_u32(&B0[nrow*SMB+bcol])); \
                LDSM4(bl, smem_u32(&B1[nrow*SMB+bcol])); \
                _Pragma("unroll") \
                for(int mi=0;mi<2;mi++){ \
                    MMA(acc[mi][g*2],   ah[mi], bh[0], bh[1]); \
                    MMA(acc[mi][g*2+1], ah[mi], bh[2], bh[3]); \
                    MMA(acc[mi][g*2],   al[mi], bh[0], bh[1]); \
                    MMA(acc[mi][g*2+1], al[mi], bh[2], bh[3]); \
                    MMA(acc[mi][g*2],   ah[mi], bl[0], bl[1]); \
                    MMA(acc[mi][g*2+1], ah[mi], bl[2], bl[3]); \
                } \
            } \
        } \
        __syncthreads(); \
    }

__global__ __launch_bounds__(256) void tgemm(
    const __nv_bfloat16* __restrict__ Ah, const __nv_bfloat16* __restrict__ Al,
    const __nv_bfloat16* __restrict__ Bh, const __nv_bfloat16* __restrict__ Bl,
    float* __restrict__ C, int N, int K, long sA, long sB, long sC)
{
    extern __shared__ __nv_bfloat16 smp[];
    Ah += (long)blockIdx.z*sA; Al += (long)blockIdx.z*sA;
    Bh += (long)blockIdx.z*sB; Bl += (long)blockIdx.z*sB;
    C  += (long)blockIdx.z*sC;
    int tid = threadIdx.x, lane = tid&31, w = tid>>5;
    long bm = (long)blockIdx.y*128, bn = (long)blockIdx.x*128;
    int wm = (w&3)*32, wn = (w>>2)*64;
    float acc[2][8][4];
    #pragma unroll
    for(int i=0;i<2;i++)
      #pragma unroll
      for(int j=0;j<8;j++)
        #pragma unroll
        for(int k=0;k<4;k++) acc[i][j][k]=0.f;
    TG_MAINLOOP(Ah,Al,Bh,Bl,K)
    #pragma unroll
    for(int mi=0;mi<2;mi++)
      #pragma unroll
      for(int ni=0;ni<8;ni++){
        long rg = bm + wm + mi*16 + (lane>>2);
        long cg = bn + wn + ni*8 + (lane&3)*2;
        *(float2*)&C[rg*N+cg]     = make_float2(acc[mi][ni][0], acc[mi][ni][1]);
        *(float2*)&C[(rg+8)*N+cg] = make_float2(acc[mi][ni][2], acc[mi][ni][3]);
      }
}

// fused recurrent step, ping-pong h buffers; G0 tile staged via SMEM (coalesced).
__global__ __launch_bounds__(256) void tlstm(
    const __nv_bfloat16* __restrict__ Ah, const __nv_bfloat16* __restrict__ Al,
    const __nv_bfloat16* __restrict__ Bh, const __nv_bfloat16* __restrict__ Bl,
    __nv_bfloat16* __restrict__ Wh, __nv_bfloat16* __restrict__ Wl, int t)
{
    extern __shared__ __nv_bfloat16 smp[];
    int tid = threadIdx.x, lane = tid&31, w = tid>>5;
    long bm = (long)blockIdx.y*128, bn = (long)blockIdx.x*128;
    int wm = (w&3)*32, wn = (w>>2)*64;
    float acc[2][8][4];
    #pragma unroll
    for(int i=0;i<2;i++)
      #pragma unroll
      for(int j=0;j<8;j++)
        #pragma unroll
        for(int k=0;k<4;k++) acc[i][j][k]=0.f;
    TG_MAINLOOP(Ah,Al,Bh,Bl,512)
    long tOff = (long)t*4096;
    // stage G0 tile coalesced into smem (stride 132 to avoid bank conflicts)
    float* Gs = (float*)smp;
    for(int i=tid;i<4096;i+=256){
        int r=i>>5, c4=(i&31)<<2;
        *(float4*)&Gs[r*132+c4] = *(const float4*)&g_G0[(tOff+bm+r)*2048 + bn + c4];
    }
    __syncthreads();
    #pragma unroll
    for(int mi=0;mi<2;mi++)
      #pragma unroll
      for(int ni=0;ni<8;ni++){
        int lcol = wn + ni*8 + (lane&3)*2;
        long gcol = bn + lcol;
        int lr0 = wm + mi*16 + (lane>>2);
        long r0 = bm + lr0;
        float b0 = g_bias[gcol], b1 = g_bias[gcol+1];
        float p00 = acc[mi][ni][0] + Gs[lr0*132+lcol]       + b0;
        float p01 = acc[mi][ni][1] + Gs[lr0*132+lcol+1]     + b1;
        float p10 = acc[mi][ni][2] + Gs[(lr0+8)*132+lcol]   + b0;
        float p11 = acc[mi][ni][3] + Gs[(lr0+8)*132+lcol+1] + b1;
        float q00 = __shfl_xor_sync(0xffffffffu,p00,1);
        float q01 = __shfl_xor_sync(0xffffffffu,p01,1);
        float q10 = __shfl_xor_sync(0xffffffffu,p10,1);
        float q11 = __shfl_xor_sync(0xffffffffu,p11,1);
        if((lane&1)==0){
            long u = gcol>>2;
            {
                float iv=sg(p00), fv=sg(p01), gv=tanhf(q00), ov=sg(q01);
                long idx=r0*512+u;
                float cc=fv*g_c[idx]+iv*gv; g_c[idx]=cc;
                float h=ov*tanhf(cc); g_h[idx]=h; bsplit(h,Wh,Wl,idx);
            }
            {
                float iv=sg(p10), fv=sg(p11), gv=tanhf(q10), ov=sg(q11);
                long idx=(r0+8)*512+u;
                float cc=fv*g_c[idx]+iv*gv; g_c[idx]=cc;
                float h=ov*tanhf(cc); g_h[idx]=h; bsplit(h,Wh,Wl,idx);
            }
        }
      }
}

__global__ void k_prep(){
    int i = blockIdx.x*256+threadIdx.x;
    if(i<2097152){ g_c[i]=0.f; g_hh[i]=__float2bfloat16(0.f); g_hl[i]=__float2bfloat16(0.f); }
}
__global__ void k_wsplit(const float* __restrict__ wih, const float* __restrict__ whh,
                         const float* __restrict__ gw, const float* __restrict__ bih,
                         const float* __restrict__ bhh){
    int i = blockIdx.x*256+threadIdx.x;
    if(i<1048576){
        int j = i>>9, k = i&511;
        int u = j>>2, gate = j&3;
        int src = (gate*512+u)*512 + k;
        bsplit(wih[src],g_wihh,g_wihl,i);
        bsplit(whh[src],g_whhh,g_whhl,i);
    }
    if(i<73728) bsplit(gw[i],g_gwh,g_gwl,i);
    if(i<2048){ int u=i>>2, gate=i&3; g_bias[i]=bih[gate*512+u]+bhh[gate*512+u]; }
}

__global__ __launch_bounds__(256) void k_conv1(const float* __restrict__ x, const float* __restrict__ w1,
    const float* __restrict__ b1, const float* __restrict__ wt, const float* __restrict__ bt)
{
    int b = blockIdx.x>>9, n = blockIdx.x&511, tid = threadIdx.x;
    __shared__ float xs[16][60]; __shared__ float sw1[1024]; __shared__ float swt[3072];
    __shared__ float sb1[64], sbt[64];
    for(int i=tid;i<960;i+=256) xs[i/60][i%60] = x[((b*16 + i/60)*512 + n)*60 + i%60];
    for(int i=tid;i<1024;i+=256) sw1[i]=w1[i];
    for(int i=tid;i<3072;i+=256) swt[i]=wt[i];
    if(tid<64){ sb1[tid]=b1[tid]; sbt[tid]=bt[tid]; }
    __syncthreads();
    for(int i=tid;i<3840;i+=256){
        int co=i/60, l=i%60;
        float a1=sb1[co], a2=sbt[co];
        #pragma unroll
        for(int ci=0;ci<16;ci++){
            float xv=xs[ci][l];
            a1 = fmaf(sw1[co*16+ci],xv,a1);
            const float* w=&swt[(co*16+ci)*3];
            if(l>0) a2 = fmaf(w[0],xs[ci][l-1],a2);
            a2 = fmaf(w[1],xv,a2);
            if(l<59) a2 = fmaf(w[2],xs[ci][l+1],a2);
        }
        int o = ((b*64+co)*512+n)*60+l;
        g_xin[o]=a1;
        float v=lr(a2);
        g_x1[o]=v;
        g_x1n[((b*512+n)*64+co)*60+l]=v;
    }
}

__global__ __launch_bounds__(256) void k_x1t(){
    int bc = blockIdx.x, nch = blockIdx.y, tid = threadIdx.x;
    __shared__ float t[64][61];
    for(int i=tid;i<3840;i+=256){
        int n=i/60, l=i%60;
        t[n][l] = g_x1[((long)bc*512 + nch*64 + n)*60 + l];
    }
    __syncthreads();
    int b = bc>>6, c = bc&63;
    for(int i=tid;i<3840;i+=256){
        int l=i>>6, n=i&63;
        if(l<60){
            long o = ((long)b*3840 + c*60 + l)*512 + nch*64 + n;
            bsplit(t[n][l], g_x1th, g_x1tl, o);
        }
    }
}

__global__ __launch_bounds__(256) void k_feat(const float* __restrict__ w31, const float* __restrict__ w32,
    const float* __restrict__ w21, const float* __restrict__ w22)
{
    int b = blockIdx.x>>9, n = blockIdx.x&511, tid = threadIdx.x;
    __shared__ float xs[64][60];
    for(int i=tid;i<3840;i+=256) xs[i/60][i%60] = g_x1[((b*64+i/60)*512+n)*60 + i%60];
    __syncthreads();
    for(int it=tid; it<512; it+=256){
        int wsel = it>>8, rem = it&255, co = rem>>2, t2 = rem&3;
        const float* W = wsel ? w32 : w31;
        float a=0.f;
        for(int c=0;c<64;c++){
            const float* wr = &W[co*768 + c*12];
            #pragma unroll
            for(int t1=0;t1<12;t1++) a = fmaf(wr[t1],xs[c][t1*4+t2],a);
        }
        float* dst = wsel ? g_fb : g_fa;
        dst[((b*16+t2)*512+n)*64+co] = a;
    }
    for(int it=tid; it<1536; it+=256){
        int wsel = it/768, rem = it%768, co = rem/12, tt = rem%12;
        const float* W = wsel ? w22 : w21;
        float a=0.f;
        #pragma unroll 8
        for(int c=0;c<64;c++) a = fmaf(W[co*64+c],xs[c][48+tt],a);
        float* dst = wsel ? g_fb : g_fa;
        dst[((b*16+4+tt)*512+n)*64+co] = a;
    }
}

__global__ __launch_bounds__(256) void k_slog(){
    int b = blockIdx.z>>4, t = blockIdx.z&15;
    int n0 = blockIdx.y*64, q0 = blockIdx.x*64, tid=threadIdx.x;
    __shared__ float As[64][65], Bs[64][65];
    const float* fa = &g_fa[((b*16+t)*512+n0)*64];
    const float* fb = &g_fb[((b*16+t)*512+q0)*64];
    for(int i=tid;i<4096;i+=256){ As[i>>6][i&63]=fa[i]; Bs[i>>6][i&63]=fb[i]; }
    __syncthreads();
    int tn = (tid>>4)*4, tq = (tid&15)*4;
    float acc[4][4][4];
    #pragma unroll
    for(int i=0;i<4;i++)
      #pragma unroll
      for(int j=0;j<4;j++)
        #pragma unroll
        for(int m=0;m<4;m++) acc[i][j][m]=0.f;
    for(int co=0;co<64;co+=4){
        #pragma unroll
        for(int m=0;m<4;m++){
            float a[4],bb[4];
            #pragma unroll
            for(int i=0;i<4;i++) a[i]=As[tn+i][co+m];
            #pragma unroll
            for(int j=0;j<4;j++) bb[j]=Bs[tq+j][co+m];
            #pragma unroll
            for(int i=0;i<4;i++)
              #pragma unroll
              for(int j=0;j<4;j++) acc[i][j][m]=fmaf(a[i],bb[j],acc[i][j][m]);
        }
    }
    #pragma unroll
    for(int i=0;i<4;i++)
      #pragma unroll
      for(int j=0;j<4;j++){
        float s = 0.25f*(sg(acc[i][j][0])+sg(acc[i][j][1])+sg(acc[i][j][2])+sg(acc[i][j][3]));
        long o = (long)(t*4096 + b*512 + n0+tn+i)*512 + q0+tq+j;
        bsplit(s, g_Sh, g_Sl, o);
    }
}

__global__ void k_adj1(const float* __restrict__ sup){
    int i = blockIdx.x*256+threadIdx.x;
    if(i>=2097152) return;
    float v = g_h[i]*sup[i];
    bsplit(v, g_a1h, g_a1l, i);
    int b = i>>18, r = i&262143;
    int q = r>>9, n = r&511;
    long oT = ((long)b<<18) + ((long)n<<9) + q;
    bsplit(v, g_aTh, g_aTl, oT);
}

__global__ void k_cheb(){
    int i = blockIdx.x*256+threadIdx.x;
    if(i>=2097152) return;
    int q = (i>>9)&511, nn = i&511;
    float v = 2.f*g_P[i] - (q==nn?1.f:0.f);
    bsplit(v, g_chh, g_chl, i);
}

__global__ void k_im2col(){
    long idx = (long)blockIdx.x*256+threadIdx.x;
    if(idx>=141557760L) return;
    int k = (int)(idx%576);
    long rg = idx/576;
    int row = (int)(rg%30720), b = (int)(rg/30720);
    int cc = k/3, j = k%3, c = cc/3, kd = cc%3;
    int q = row/60, l = row%60, li = l+j-1;
    float v=0.f;
    if(li>=0 && li<60){
        if(kd==0) v = g_x1n[((b*512+q)*64+c)*60+li];
        else      v = g_xg[((long)(b*2+kd-1)*512+q)*3840 + c*60+li];
    }
    bsplit(v, g_colh, g_coll, idx);
}

__global__ void k_comb(const float* __restrict__ gb_){
    int idx = blockIdx.x*256+threadIdx.x;
    if(idx>=15728640) return;
    int l = idx%60, n = (idx/60)&511, c = (idx/30720)&63, b = idx/PER_B;
    float f = g_cv[(long)(b*128+c)*30720 + n*60+l] + gb_[c];
    float g = g_cv[(long)(b*128+c+64)*30720 + n*60+l] + gb_[c+64];
    g_x1b[idx] = sg(g)*lr(f);
}

__global__ __launch_bounds__(256) void k_tf1(const float* __restrict__ w){
    int b = blockIdx.x>>9, n = blockIdx.x&511, tid = threadIdx.x;
    __shared__ float xs[64][60]; __shared__ float ws[64];
    for(int i=tid;i<3840;i+=256) xs[i/60][i%60] = g_x1b[((b*64+i/60)*512+n)*60+i%60];
    if(tid<64) ws[tid]=w[tid];
    __syncthreads();
    if(tid<60){
        float a=0.f;
        #pragma unroll 8
        for(int c=0;c<64;c++) a = fmaf(ws[c],xs[c][tid],a);
        g_tf1[(b*60+tid)*512+n]=a;
    }
}

__global__ void k_tf2(const float* __restrict__ w){
    int idx = blockIdx.x*256+threadIdx.x;
    if(idx>=30720) return;
    int l = idx%60, c = (idx/60)&63, b = idx/3840;
    const float* xp = &g_x1b[((long)(b*64+c)*512)*60 + l];
    float a=0.f;
    for(int n=0;n<512;n++) a = fmaf(w[n],xp[n*60],a);
    g_tf2[idx]=a;
}

__global__ __launch_bounds__(256) void k_tatt(const float* __restrict__ tw,
        const float* __restrict__ tb, const float* __restrict__ tv){
    int b = blockIdx.x, tid = threadIdx.x;
    __shared__ float tmp[60][64], f2s[64][60], lgs[60][60];
    for(int i=tid;i<3840;i+=256) f2s[i/60][i%60] = g_tf2[b*3840+i];
    for(int i=tid;i<3840;i+=256){
        int l=i>>6, c=i&63;
        const float* f1 = &g_tf1[(b*60+l)*512];
        float a=0.f;
        for(int n=0;n<512;n++) a = fmaf(f1[n],tw[n*64+c],a);
        tmp[l][c]=a;
    }
    __syncthreads();
    for(int i=tid;i<3600;i+=256){
        int l=i/60, q=i%60;
        float a=tb[l*60+q];
        #pragma unroll
        for(int c=0;c<64;c++) a = fmaf(tmp[l][c],f2s[c][q],a);
        lgs[l][q]=sg(a);
    }
    __syncthreads();
    for(int i=tid;i<3600;i+=256){
        int ii=i/60, t=i%60;
        float a=0.f;
        #pragma unroll 10
        for(int q=0;q<60;q++) a = fmaf(tv[ii*60+q],lgs[q][t],a);
        g_lg2[b*3600+i]=a;
    }
}

__global__ void k_bn1(const float* __restrict__ gam, const float* __restrict__ bet){
    int t = threadIdx.x;
    if(t>=60) return;
    double s=0, s2=0;
    for(int b=0;b<8;b++)
        for(int i=0;i<60;i++){
            double v = (double)g_lg2[b*3600+i*60+t]; s+=v; s2+=v*v;
        }
    double mu=s/480.0, var=s2/480.0-mu*mu;
    float scv = gam[t]*rsqrtf((float)var+1e-5f);
    g_sc[t]=scv; g_sh[t]=bet[t]-(float)mu*scv;
}

__device__ __forceinline__ int blk4(int i){ return i<12?0:(i<24?1:(i<36?2:3)); }

__global__ void k_bn2(){
    int row = blockIdx.x;
    int b = row/60, i = row%60, tid=threadIdx.x;
    __shared__ float v[60];
    if(tid<60){
        float x = g_lg2[b*3600+i*60+tid]*g_sc[tid]+g_sh[tid];
        if(blk4(i)!=blk4(tid)) x = -1e13f;
        v[tid]=x;
    }
    __syncthreads();
    if(tid==0){
        float m=-1e30f;
        for(int t=0;t<60;t++) m=fmaxf(m,v[t]);
        float s=0.f;
        for(int t=0;t<60;t++){ float e=__expf(v[t]-m); v[t]=e; s+=e; }
        float inv=1.f/s;
        for(int t=0;t<60;t++) g_Tc[b*3600+i*60+t]=v[t]*inv;
    }
}

__global__ __launch_bounds__(256) void k_x2(){
    int b = blockIdx.x>>9, n = blockIdx.x&511, tid=threadIdx.x;
    __shared__ float Tcs[60][60], xs[64][60];
    __shared__ double rs[256], rs2[256];
    for(int i=tid;i<3600;i+=256) Tcs[i/60][i%60]=g_Tc[b*3600+i];
    for(int i=tid;i<3840;i+=256) xs[i/60][i%60]=g_x1b[((b*64+i/60)*512+n)*60+i%60];
    __syncthreads();
    double ls=0, ls2=0;
    for(int i=tid;i<3840;i+=256){
        int c=i/60, q=i%60;
        float a=0.f;
        #pragma unroll
        for(int l=0;l<60;l++) a = fmaf(xs[c][l],Tcs[q][l],a);
        int o = ((b*64+c)*512+n)*60+q;
        float y = lr(a)+g_xin[o];
        g_y[o]=y;
        ls += (double)y; ls2 += (double)y*(double)y;
    }
    rs[tid]=ls; rs2[tid]=ls2;
    __syncthreads();
    for(int s=128;s>0;s>>=1){
        if(tid<s){ rs[tid]+=rs[tid+s]; rs2[tid]+=rs2[tid+s]; }
        __syncthreads();
    }
    if(tid==0){ g_part[blockIdx.x*2]=rs[0]; g_part[blockIdx.x*2+1]=rs2[0]; }
}

__global__ void k_lnred(){
    int b = blockIdx.x, tid = threadIdx.x;
    __shared__ double rs[256], rs2[256];
    rs[tid]  = g_part[(b*512+tid)*2]   + g_part[(b*512+tid+256)*2];
    rs2[tid] = g_part[(b*512+tid)*2+1] + g_part[(b*512+tid+256)*2+1];
    __syncthreads();
    for(int k=128;k>0;k>>=1){
        if(tid<k){ rs[tid]+=rs[tid+k]; rs2[tid]+=rs2[tid+k]; }
        __syncthreads();
    }
    if(tid==0){
        double mu = rs[0]/1966080.0, var = rs2[0]/1966080.0 - mu*mu;
        g_mu[b]=(float)mu; g_inv[b]=(float)(1.0/sqrt(var+1e-5));
    }
}

__global__ void k_lnout(const float* __restrict__ lg_, const float* __restrict__ lb_, float* __restrict__ out){
    int idx = blockIdx.x*256+threadIdx.x;
    if(idx>=15728640) return;
    int b = idx/PER_B, i = idx%PER_B;
    out[idx] = (g_y[idx]-g_mu[b])*g_inv[b]*lg_[i]+lb_[i];
}

__global__ void k_tail(float* __restrict__ out){
    int idx = blockIdx.x*256+threadIdx.x;
    if(idx<2097152) out[15728640+idx]=g_h[idx];
    else if(idx<2125952) out[15728640+idx]=g_Tc[idx-2097152];
}

extern "C" void kernel_launch(void* const* d_in, const int* in_sizes, int n_in,
                              void* d_out, int out_size) {
    const float* x       =(const float*)d_in[0];
    const float* supports=(const float*)d_in[1];
    const float* conv1_w =(const float*)d_in[2];
    const float* conv1_b =(const float*)d_in[3];
    const float* tconv_w =(const float*)d_in[4];
    const float* tconv_b =(const float*)d_in[5];
    const float* s3_w1   =(const float*)d_in[6];
    const float* s3_w2   =(const float*)d_in[7];
    const float* s2_w1   =(const float*)d_in[8];
    const float* s2_w2   =(const float*)d_in[9];
    const float* wih     =(const float*)d_in[10];
    const float* whh     =(const float*)d_in[11];
    const float* bih     =(const float*)d_in[12];
    const float* bhh     =(const float*)d_in[13];
    const float* gcn_w   =(const float*)d_in[14];
    const float* gcn_b   =(const float*)d_in[15];
    const float* t_w1    =(const float*)d_in[16];
    const float* t_w2    =(const float*)d_in[17];
    const float* t_w     =(const float*)d_in[18];
    const float* t_b     =(const float*)d_in[19];
    const float* t_v     =(const float*)d_in[20];
    const float* t_bn_g  =(const float*)d_in[21];
    const float* t_bn_b  =(const float*)d_in[22];
    const float* ln_g    =(const float*)d_in[23];
    const float* ln_b    =(const float*)d_in[24];
    float* out=(float*)d_out;

    float *pG0,*pP,*pxg,*pcv;
    __nv_bfloat16 *pSh,*pSl,*pwihh,*pwihl,*pwhhh,*pwhhl,*phh,*phl,*phh2,*phl2;
    __nv_bfloat16 *pa1h,*pa1l,*paTh,*paTl,*pchh,*pchl,*px1th,*px1tl,*pcolh,*pcoll,*pgwh,*pgwl;
    cudaGetSymbolAddress((void**)&pG0,  g_G0);
    cudaGetSymbolAddress((void**)&pP,   g_P);
    cudaGetSymbolAddress((void**)&pxg,  g_xg);
    cudaGetSymbolAddress((void**)&pcv,  g_cv);
    cudaGetSymbolAddress((void**)&pSh,  g_Sh);
    cudaGetSymbolAddress((void**)&pSl,  g_Sl);
    cudaGetSymbolAddress((void**)&pwihh,g_wihh);
    cudaGetSymbolAddress((void**)&pwihl,g_wihl);
    cudaGetSymbolAddress((void**)&pwhhh,g_whhh);
    cudaGetSymbolAddress((void**)&pwhhl,g_whhl);
    cudaGetSymbolAddress((void**)&phh,  g_hh);
    cudaGetSymbolAddress((void**)&phl,  g_hl);
    cudaGetSymbolAddress((void**)&phh2, g_hh2);
    cudaGetSymbolAddress((void**)&phl2, g_hl2);
    cudaGetSymbolAddress((void**)&pa1h, g_a1h);
    cudaGetSymbolAddress((void**)&pa1l, g_a1l);
    cudaGetSymbolAddress((void**)&paTh, g_aTh);
    cudaGetSymbolAddress((void**)&paTl, g_aTl);
    cudaGetSymbolAddress((void**)&pchh, g_chh);
    cudaGetSymbolAddress((void**)&pchl, g_chl);
    cudaGetSymbolAddress((void**)&px1th,g_x1th);
    cudaGetSymbolAddress((void**)&px1tl,g_x1tl);
    cudaGetSymbolAddress((void**)&pcolh,g_colh);
    cudaGetSymbolAddress((void**)&pcoll,g_coll);
    cudaGetSymbolAddress((void**)&pgwh, g_gwh);
    cudaGetSymbolAddress((void**)&pgwl, g_gwl);

    cudaFuncSetAttribute(tgemm, cudaFuncAttributeMaxDynamicSharedMemorySize, 81920);
    cudaFuncSetAttribute(tlstm, cudaFuncAttributeMaxDynamicSharedMemorySize, 81920);
    const int TS = 81920;

    k_prep<<<8192,256>>>();
    k_wsplit<<<4096,256>>>(wih, whh, gcn_w, bih, bhh);
    k_conv1<<<4096,256>>>(x, conv1_w, conv1_b, tconv_w, tconv_b);
    k_x1t<<<dim3(512,8),256>>>();
    k_feat<<<4096,256>>>(s3_w1,s3_w2,s2_w1,s2_w2);
    k_slog<<<dim3(8,8,128),256>>>();
    tgemm<<<dim3(16,512,1),256,TS>>>(pSh,pSl,pwihh,pwihl,pG0,2048,512,0,0,0);
    for(int t=0;t<16;t++){
        __nv_bfloat16 *rh = (t&1)? phh2 : phh,  *rl = (t&1)? phl2 : phl;
        __nv_bfloat16 *wh = (t&1)? phh  : phh2, *wl = (t&1)? phl  : phl2;
        tlstm<<<dim3(16,32),256,TS>>>(rh,rl,pwhhh,pwhhl,wh,wl,t);
    }
    k_adj1<<<8192,256>>>(supports);
    tgemm<<<dim3(4,4,8),256,TS>>>(pa1h,pa1l,paTh,paTl,pP,512,512,262144,262144,262144);
    k_cheb<<<8192,256>>>();
    tgemm<<<dim3(30,4,8),256,TS>>>(pa1h,pa1l,px1th,px1tl,pxg,        3840,512,262144,1966080,3932160);
    tgemm<<<dim3(30,4,8),256,TS>>>(pchh,pchl,px1th,px1tl,pxg+1966080,3840,512,262144,1966080,3932160);
    k_im2col<<<552960,256>>>();
    tgemm<<<dim3(240,1,8),256,TS>>>(pgwh,pgwl,pcolh,pcoll,pcv,30720,576,0,17694720,3932160);
    k_comb<<<61440,256>>>(gcn_b);
    k_tf1<<<4096,256>>>(t_w1);
    k_tf2<<<120,256>>>(t_w2);
    k_tatt<<<8,256>>>(t_w,t_b,t_v);
    k_bn1<<<1,64>>>(t_bn_g,t_bn_b);
    k_bn2<<<480,64>>>();
    k_x2<<<4096,256>>>();
    k_lnred<<<8,256>>>();
    k_lnout<<<61440,256>>>(ln_g,ln_b,out);
    if(out_size >= 17854592) k_tail<<<8306,256>>>(out);
}

// round 16
// speedup vs baseline: 1.0491x; 1.0445x over previous
#include <cuda_runtime.h>
#include <cuda_bf16.h>
#include <math.h>
#include <stdint.h>

#define PER_B 1966080
#define SMB 40

__device__ float g_xin[15728640], g_x1[15728640], g_x1n[15728640];
__device__ float g_fa[4194304], g_fb[4194304];
__device__ __nv_bfloat16 g_Sh[33554432], g_Sl[33554432];
__device__ __nv_bfloat16 g_wihh[1048576], g_wihl[1048576], g_whhh[1048576], g_whhl[1048576];
__device__ __nv_bfloat16 g_hh[2097152], g_hl[2097152];
__device__ __nv_bfloat16 g_a1h[2097152], g_a1l[2097152], g_aTh[2097152], g_aTl[2097152];
__device__ __nv_bfloat16 g_chh[2097152], g_chl[2097152];
__device__ __nv_bfloat16 g_x1th[15728640], g_x1tl[15728640];
__device__ __nv_bfloat16 g_colh[141557760], g_coll[141557760];
__device__ __nv_bfloat16 g_gwh[73728], g_gwl[73728];
__device__ float g_bias[2048];
__device__ float g_G0[134217728];
__device__ float g_h[2097152], g_c[2097152], g_gb[8388608];
__device__ float g_P[2097152];
__device__ float g_xg[31457280];
__device__ float g_cv[31457280];
__device__ float g_x1b[15728640];
__device__ float g_tf1[245760], g_tf2[30720];
__device__ float g_lg2[28800];
__device__ float g_sc[60], g_sh[60];
__device__ float g_Tc[28800];
__device__ float g_y[15728640];
__device__ double g_part[8192];
__device__ float g_mu[8], g_inv[8];

__device__ __forceinline__ float sg(float x){ return 1.f/(1.f+__expf(-x)); }
__device__ __forceinline__ float lr(float x){ return x>0.f?x:0.01f*x; }
__device__ __forceinline__ void bsplit(float v, __nv_bfloat16* H, __nv_bfloat16* L, long o){
    __nv_bfloat16 h = __float2bfloat16(v);
    H[o]=h; L[o]=__float2bfloat16(v-__bfloat162float(h));
}
__device__ __forceinline__ uint32_t smem_u32(const void* p){
    uint32_t a; asm("{ .reg .u64 t; cvta.to.shared.u64 t, %1; cvt.u32.u64 %0, t; }" : "=r"(a) : "l"(p)); return a;
}
#define LDSM4(r,addr) asm volatile("ldmatrix.sync.aligned.m8n8.x4.shared.b16 {%0,%1,%2,%3}, [%4];" \
  : "=r"((r)[0]),"=r"((r)[1]),"=r"((r)[2]),"=r"((r)[3]) : "r"(addr))
#define MMA(c,a,b0,b1) asm volatile("mma.sync.aligned.m16n8k16.row.col.f32.bf16.bf16.f32 " \
  "{%0,%1,%2,%3},{%4,%5,%6,%7},{%8,%9},{%0,%1,%2,%3};" \
  : "+f"((c)[0]),"+f"((c)[1]),"+f"((c)[2]),"+f"((c)[3]) \
  : "r"((a)[0]),"r"((a)[1]),"r"((a)[2]),"r"((a)[3]),"r"(b0),"r"(b1))
#define CPA(d,s) asm volatile("cp.async.cg.shared.global [%0],[%1],16;" :: "r"(d),"l"(s))
#define CPC()    asm volatile("cp.async.commit_group;" ::: "memory")
#define CPW0()   asm volatile("cp.async.wait_group 0;" ::: "memory")
#define CPW1()   asm volatile("cp.async.wait_group 1;" ::: "memory")

// C[M,N] = A[M,K] @ B[N,K]^T, split-bf16 (AhBh+AlBh+AhBl), fp32 accum, batched via z.
// cp.async double-buffered mainloop.
__global__ __launch_bounds__(256) void tgemm(
    const __nv_bfloat16* __restrict__ Ah, const __nv_bfloat16* __restrict__ Al,
    const __nv_bfloat16* __restrict__ Bh, const __nv_bfloat16* __restrict__ Bl,
    float* __restrict__ C, int N, int K, long sA, long sB, long sC)
{
    extern __shared__ __nv_bfloat16 smp[];
    Ah += (long)blockIdx.z*sA; Al += (long)blockIdx.z*sA;
    Bh += (long)blockIdx.z*sB; Bl += (long)blockIdx.z*sB;
    C  += (long)blockIdx.z*sC;
    int tid = threadIdx.x, lane = tid&31, w = tid>>5;
    long bm = (long)blockIdx.y*128, bn = (long)blockIdx.x*128;
    int wm = (w&3)*32, wn = (w>>2)*64;
    float acc[2][8][4];
    #pragma unroll
    for(int i=0;i<2;i++)
      #pragma unroll
      for(int j=0;j<8;j++)
        #pragma unroll
        for(int k=0;k<4;k++) acc[i][j][k]=0.f;

    auto ldst = [&](int st, int k0){
        __nv_bfloat16* S = smp + st*20480;
        for(int i=tid;i<512;i+=256){
            int r=i>>2, u=i&3;
            uint32_t d = smem_u32(&S[r*SMB+u*8]);
            CPA(d,       Ah+(bm+r)*K+k0+u*8);
            CPA(d+10240, Al+(bm+r)*K+k0+u*8);
            CPA(d+20480, Bh+(bn+r)*K+k0+u*8);
            CPA(d+30720, Bl+(bn+r)*K+k0+u*8);
        }
    };

    int nc = K>>5;
    ldst(0,0); CPC();
    for(int c=0;c<nc;c++){
        int cur = c&1;
        if(c+1<nc){ ldst(cur^1,(c+1)<<5); CPC(); CPW1(); }
        else CPW0();
        __syncthreads();
        __nv_bfloat16* S = smp + cur*20480;
        const __nv_bfloat16 *A0=S, *A1=S+5120, *B0=S+10240, *B1=S+15360;
        #pragma unroll
        for(int ks=0;ks<2;ks++){
            uint32_t ah[2][4], al[2][4];
            int arow = wm + (lane&15), acol = ks*16 + (lane>>4)*8;
            #pragma unroll
            for(int mi=0;mi<2;mi++){
                LDSM4(ah[mi], smem_u32(&A0[(arow+mi*16)*SMB+acol]));
                LDSM4(al[mi], smem_u32(&A1[(arow+mi*16)*SMB+acol]));
            }
            #pragma unroll
            for(int g=0;g<4;g++){
                uint32_t bh[4], bl[4];
                int nrow = wn + g*16 + ((lane>>4)*8) + (lane&7);
                int bcol = ks*16 + ((lane>>3)&1)*8;
                LDSM4(bh, smem_u32(&B0[nrow*SMB+bcol]));
                LDSM4(bl, smem_u32(&B1[nrow*SMB+bcol]));
                #pragma unroll
                for(int mi=0;mi<2;mi++){
                    MMA(acc[mi][g*2],   ah[mi], bh[0], bh[1]);
                    MMA(acc[mi][g*2+1], ah[mi], bh[2], bh[3]);
                    MMA(acc[mi][g*2],   al[mi], bh[0], bh[1]);
                    MMA(acc[mi][g*2+1], al[mi], bh[2], bh[3]);
                    MMA(acc[mi][g*2],   ah[mi], bl[0], bl[1]);
                    MMA(acc[mi][g*2+1], ah[mi], bl[2], bl[3]);
                }
            }
        }
        __syncthreads();
    }
    #pragma unroll
    for(int mi=0;mi<2;mi++)
      #pragma unroll
      for(int ni=0;ni<8;ni++){
        long rg = bm + wm + mi*16 + (lane>>2);
        long cg = bn + wn + ni*8 + (lane&3)*2;
        *(float2*)&C[rg*N+cg]     = make_float2(acc[mi][ni][0], acc[mi][ni][1]);
        *(float2*)&C[(rg+8)*N+cg] = make_float2(acc[mi][ni][2], acc[mi][ni][3]);
      }
}

__global__ void k_prep(){
    int i = blockIdx.x*256+threadIdx.x;
    if(i<2097152){ g_c[i]=0.f; g_hh[i]=__float2bfloat16(0.f); g_hl[i]=__float2bfloat16(0.f); }
}
__global__ void k_wsplit(const float* __restrict__ wih, const float* __restrict__ whh,
                         const float* __restrict__ gw, const float* __restrict__ bih,
                         const float* __restrict__ bhh){
    int i = blockIdx.x*256+threadIdx.x;
    if(i<1048576){ bsplit(wih[i],g_wihh,g_wihl,i); bsplit(whh[i],g_whhh,g_whhl,i); }
    if(i<73728) bsplit(gw[i],g_gwh,g_gwl,i);
    if(i<2048) g_bias[i]=bih[i]+bhh[i];
}

__global__ __launch_bounds__(256) void k_conv1(const float* __restrict__ x, const float* __restrict__ w1,
    const float* __restrict__ b1, const float* __restrict__ wt, const float* __restrict__ bt)
{
    int b = blockIdx.x>>9, n = blockIdx.x&511, tid = threadIdx.x;
    __shared__ float xs[16][60]; __shared__ float sw1[1024]; __shared__ float swt[3072];
    __shared__ float sb1[64], sbt[64];
    for(int i=tid;i<960;i+=256) xs[i/60][i%60] = x[((b*16 + i/60)*512 + n)*60 + i%60];
    for(int i=tid;i<1024;i+=256) sw1[i]=w1[i];
    for(int i=tid;i<3072;i+=256) swt[i]=wt[i];
    if(tid<64){ sb1[tid]=b1[tid]; sbt[tid]=bt[tid]; }
    __syncthreads();
    for(int i=tid;i<3840;i+=256){
        int co=i/60, l=i%60;
        float a1=sb1[co], a2=sbt[co];
        #pragma unroll
        for(int ci=0;ci<16;ci++){
            float xv=xs[ci][l];
            a1 = fmaf(sw1[co*16+ci],xv,a1);
            const float* w=&swt[(co*16+ci)*3];
            if(l>0) a2 = fmaf(w[0],xs[ci][l-1],a2);
            a2 = fmaf(w[1],xv,a2);
            if(l<59) a2 = fmaf(w[2],xs[ci][l+1],a2);
        }
        int o = ((b*64+co)*512+n)*60+l;
        g_xin[o]=a1;
        float v=lr(a2);
        g_x1[o]=v;
        g_x1n[((b*512+n)*64+co)*60+l]=v;
    }
}

__global__ __launch_bounds__(256) void k_x1t(){
    int bc = blockIdx.x, nch = blockIdx.y, tid = threadIdx.x;
    __shared__ float t[64][61];
    for(int i=tid;i<3840;i+=256){
        int n=i/60, l=i%60;
        t[n][l] = g_x1[((long)bc*512 + nch*64 + n)*60 + l];
    }
    __syncthreads();
    int b = bc>>6, c = bc&63;
    for(int i=tid;i<3840;i+=256){
        int l=i>>6, n=i&63;
        if(l<60){
            long o = ((long)b*3840 + c*60 + l)*512 + nch*64 + n;
            bsplit(t[n][l], g_x1th, g_x1tl, o);
        }
    }
}

__global__ __launch_bounds__(256) void k_feat(const float* __restrict__ w31, const float* __restrict__ w32,
    const float* __restrict__ w21, const float* __restrict__ w22)
{
    int b = blockIdx.x>>9, n = blockIdx.x&511, tid = threadIdx.x;
    __shared__ float xs[64][60];
    for(int i=tid;i<3840;i+=256) xs[i/60][i%60] = g_x1[((b*64+i/60)*512+n)*60 + i%60];
    __syncthreads();
    for(int it=tid; it<512; it+=256){
        int wsel = it>>8, rem = it&255, co = rem>>2, t2 = rem&3;
        const float* W = wsel ? w32 : w31;
        float a=0.f;
        for(int c=0;c<64;c++){
            const float* wr = &W[co*768 + c*12];
            #pragma unroll
            for(int t1=0;t1<12;t1++) a = fmaf(wr[t1],xs[c][t1*4+t2],a);
        }
        float* dst = wsel ? g_fb : g_fa;
        dst[((b*16+t2)*512+n)*64+co] = a;
    }
    for(int it=tid; it<1536; it+=256){
        int wsel = it/768, rem = it%768, co = rem/12, tt = rem%12;
        const float* W = wsel ? w22 : w21;
        float a=0.f;
        #pragma unroll 8
        for(int c=0;c<64;c++) a = fmaf(W[co*64+c],xs[c][48+tt],a);
        float* dst = wsel ? g_fb : g_fa;
        dst[((b*16+4+tt)*512+n)*64+co] = a;
    }
}

// higher-occupancy slog: 32x32 tile, 2x2x4 accumulators/thread
__global__ __launch_bounds__(256) void k_slog(){
    int b = blockIdx.z>>4, t = blockIdx.z&15;
    int n0 = blockIdx.y*32, q0 = blockIdx.x*32, tid=threadIdx.x;
    __shared__ float As[32][65], Bs[32][65];
    const float* fa = &g_fa[((b*16+t)*512+n0)*64];
    const float* fb = &g_fb[((b*16+t)*512+q0)*64];
    for(int i=tid;i<2048;i+=256){ As[i>>6][i&63]=fa[i]; Bs[i>>6][i&63]=fb[i]; }
    __syncthreads();
    int tn = (tid>>4)*2, tq = (tid&15)*2;
    float acc[2][2][4];
    #pragma unroll
    for(int i=0;i<2;i++)
      #pragma unroll
      for(int j=0;j<2;j++)
        #pragma unroll
        for(int m=0;m<4;m++) acc[i][j][m]=0.f;
    for(int co=0;co<64;co+=4){
        #pragma unroll
        for(int m=0;m<4;m++){
            float a[2],bb[2];
            #pragma unroll
            for(int i=0;i<2;i++) a[i]=As[tn+i][co+m];
            #pragma unroll
            for(int j=0;j<2;j++) bb[j]=Bs[tq+j][co+m];
            #pragma unroll
            for(int i=0;i<2;i++)
              #pragma unroll
              for(int j=0;j<2;j++) acc[i][j][m]=fmaf(a[i],bb[j],acc[i][j][m]);
        }
    }
    #pragma unroll
    for(int i=0;i<2;i++)
      #pragma unroll
      for(int j=0;j<2;j++){
        float s = 0.25f*(sg(acc[i][j][0])+sg(acc[i][j][1])+sg(acc[i][j][2])+sg(acc[i][j][3]));
        long o = (long)(t*4096 + b*512 + n0+tn+i)*512 + q0+tq+j;
        bsplit(s, g_Sh, g_Sl, o);
    }
}

__global__ void k_cell(int t){
    int idx = blockIdx.x*256+threadIdx.x;
    if(idx>=2097152) return;
    int r = idx>>9, u = idx&511;
    const float* G = &g_G0[((long)t*4096+r)*2048];
    const float* Gb = &g_gb[r*2048];
    float iv = sg(G[u]      + Gb[u]      + g_bias[u]);
    float fv = sg(G[u+512]  + Gb[u+512]  + g_bias[u+512]);
    float gv = tanhf(G[u+1024]+ Gb[u+1024]+ g_bias[u+1024]);
    float ov = sg(G[u+1536] + Gb[u+1536] + g_bias[u+1536]);
    float c = fv*g_c[idx] + iv*gv;
    g_c[idx] = c;
    float h = ov*tanhf(c);
    g_h[idx] = h;
    bsplit(h, g_hh, g_hl, idx);
}

__global__ void k_adj1(const float* __restrict__ sup){
    int i = blockIdx.x*256+threadIdx.x;
    if(i>=2097152) return;
    float v = g_h[i]*sup[i];
    bsplit(v, g_a1h, g_a1l, i);
    int b = i>>18, r = i&262143;
    int q = r>>9, n = r&511;
    long oT = ((long)b<<18) + ((long)n<<9) + q;
    bsplit(v, g_aTh, g_aTl, oT);
}

__global__ void k_cheb(){
    int i = blockIdx.x*256+threadIdx.x;
    if(i>=2097152) return;
    int q = (i>>9)&511, nn = i&511;
    float v = 2.f*g_P[i] - (q==nn?1.f:0.f);
    bsplit(v, g_chh, g_chl, i);
}

__global__ void k_im2col(){
    long idx = (long)blockIdx.x*256+threadIdx.x;
    if(idx>=141557760L) return;
    int k = (int)(idx%576);
    long rg = idx/576;
    int row = (int)(rg%30720), b = (int)(rg/30720);
    int cc = k/3, j = k%3, c = cc/3, kd = cc%3;
    int q = row/60, l = row%60, li = l+j-1;
    float v=0.f;
    if(li>=0 && li<60){
        if(kd==0) v = g_x1n[((b*512+q)*64+c)*60+li];
        else      v = g_xg[((long)(b*2+kd-1)*512+q)*3840 + c*60+li];
    }
    bsplit(v, g_colh, g_coll, idx);
}

__global__ void k_comb(const float* __restrict__ gb_){
    int idx = blockIdx.x*256+threadIdx.x;
    if(idx>=15728640) return;
    int l = idx%60, n = (idx/60)&511, c = (idx/30720)&63, b = idx/PER_B;
    float f = g_cv[(long)(b*128+c)*30720 + n*60+l] + gb_[c];
    float g = g_cv[(long)(b*128+c+64)*30720 + n*60+l] + gb_[c+64];
    g_x1b[idx] = sg(g)*lr(f);
}

__global__ __launch_bounds__(256) void k_tf1(const float* __restrict__ w){
    int b = blockIdx.x>>9, n = blockIdx.x&511, tid = threadIdx.x;
    __shared__ float xs[64][60]; __shared__ float ws[64];
    for(int i=tid;i<3840;i+=256) xs[i/60][i%60] = g_x1b[((b*64+i/60)*512+n)*60+i%60];
    if(tid<64) ws[tid]=w[tid];
    __syncthreads();
    if(tid<60){
        float a=0.f;
        #pragma unroll 8
        for(int c=0;c<64;c++) a = fmaf(ws[c],xs[c][tid],a);
        g_tf1[(b*60+tid)*512+n]=a;
    }
}

__global__ void k_tf2(const float* __restrict__ w){
    int idx = blockIdx.x*256+threadIdx.x;
    if(idx>=30720) return;
    int l = idx%60, c = (idx/60)&63, b = idx/3840;
    const float* xp = &g_x1b[((long)(b*64+c)*512)*60 + l];
    float a=0.f;
    for(int n=0;n<512;n++) a = fmaf(w[n],xp[n*60],a);
    g_tf2[idx]=a;
}

__global__ __launch_bounds__(256) void k_tatt(const float* __restrict__ tw,
        const float* __restrict__ tb, const float* __restrict__ tv){
    int b = blockIdx.x, tid = threadIdx.x;
    __shared__ float tmp[60][64], f2s[64][60], lgs[60][60];
    for(int i=tid;i<3840;i+=256) f2s[i/60][i%60] = g_tf2[b*3840+i];
    for(int i=tid;i<3840;i+=256){
        int l=i>>6, c=i&63;
        const float* f1 = &g_tf1[(b*60+l)*512];
        float a=0.f;
        for(int n=0;n<512;n++) a = fmaf(f1[n],tw[n*64+c],a);
        tmp[l][c]=a;
    }
    __syncthreads();
    for(int i=tid;i<3600;i+=256){
        int l=i/60, q=i%60;
        float a=tb[l*60+q];
        #pragma unroll
        for(int c=0;c<64;c++) a = fmaf(tmp[l][c],f2s[c][q],a);
        lgs[l][q]=sg(a);
    }
    __syncthreads();
    for(int i=tid;i<3600;i+=256){
        int ii=i/60, t=i%60;
        float a=0.f;
        #pragma unroll 10
        for(int q=0;q<60;q++) a = fmaf(tv[ii*60+q],lgs[q][t],a);
        g_lg2[b*3600+i]=a;
    }
}

__global__ void k_bn1(const float* __restrict__ gam, const float* __restrict__ bet){
    int t = threadIdx.x;
    if(t>=60) return;
    double s=0, s2=0;
    for(int b=0;b<8;b++)
        for(int i=0;i<60;i++){
            double v = (double)g_lg2[b*3600+i*60+t]; s+=v; s2+=v*v;
        }
    double mu=s/480.0, var=s2/480.0-mu*mu;
    float scv = gam[t]*rsqrtf((float)var+1e-5f);
    g_sc[t]=scv; g_sh[t]=bet[t]-(float)mu*scv;
}

__device__ __forceinline__ int blk4(int i){ return i<12?0:(i<24?1:(i<36?2:3)); }

__global__ void k_bn2(){
    int row = blockIdx.x;
    int b = row/60, i = row%60, tid=threadIdx.x;
    __shared__ float v[60];
    if(tid<60){
        float x = g_lg2[b*3600+i*60+tid]*g_sc[tid]+g_sh[tid];
        if(blk4(i)!=blk4(tid)) x = -1e13f;
        v[tid]=x;
    }
    __syncthreads();
    if(tid==0){
        float m=-1e30f;
        for(int t=0;t<60;t++) m=fmaxf(m,v[t]);
        float s=0.f;
        for(int t=0;t<60;t++){ float e=__expf(v[t]-m); v[t]=e; s+=e; }
        float inv=1.f/s;
        for(int t=0;t<60;t++) g_Tc[b*3600+i*60+t]=v[t]*inv;
    }
}

__global__ __launch_bounds__(256) void k_x2(){
    int b = blockIdx.x>>9, n = blockIdx.x&511, tid=threadIdx.x;
    __shared__ float Tcs[60][60], xs[64][60];
    __shared__ double rs[256], rs2[256];
    for(int i=tid;i<3600;i+=256) Tcs[i/60][i%60]=g_Tc[b*3600+i];
    for(int i=tid;i<3840;i+=256) xs[i/60][i%60]=g_x1b[((b*64+i/60)*512+n)*60+i%60];
    __syncthreads();
    double ls=0, ls2=0;
    for(int i=tid;i<3840;i+=256){
        int c=i/60, q=i%60;
        float a=0.f;
        #pragma unroll
        for(int l=0;l<60;l++) a = fmaf(xs[c][l],Tcs[q][l],a);
        int o = ((b*64+c)*512+n)*60+q;
        float y = lr(a)+g_xin[o];
        g_y[o]=y;
        ls += (double)y; ls2 += (double)y*(double)y;
    }
    rs[tid]=ls; rs2[tid]=ls2;
    __syncthreads();
    for(int s=128;s>0;s>>=1){
        if(tid<s){ rs[tid]+=rs[tid+s]; rs2[tid]+=rs2[tid+s]; }
        __syncthreads();
    }
    if(tid==0){ g_part[blockIdx.x*2]=rs[0]; g_part[blockIdx.x*2+1]=rs2[0]; }
}

__global__ void k_lnred(){
    int b = blockIdx.x, tid = threadIdx.x;
    __shared__ double rs[256], rs2[256];
    rs[tid]  = g_part[(b*512+tid)*2]   + g_part[(b*512+tid+256)*2];
    rs2[tid] = g_part[(b*512+tid)*2+1] + g_part[(b*512+tid+256)*2+1];
    __syncthreads();
    for(int k=128;k>0;k>>=1){
        if(tid<k){ rs[tid]+=rs[tid+k]; rs2[tid]+=rs2[tid+k]; }
        __syncthreads();
    }
    if(tid==0){
        double mu = rs[0]/1966080.0, var = rs2[0]/1966080.0 - mu*mu;
        g_mu[b]=(float)mu; g_inv[b]=(float)(1.0/sqrt(var+1e-5));
    }
}

__global__ void k_lnout(const float* __restrict__ lg_, const float* __restrict__ lb_, float* __restrict__ out){
    int idx = blockIdx.x*256+threadIdx.x;
    if(idx>=15728640) return;
    int b = idx/PER_B, i = idx%PER_B;
    out[idx] = (g_y[idx]-g_mu[b])*g_inv[b]*lg_[i]+lb_[i];
}

__global__ void k_tail(float* __restrict__ out){
    int idx = blockIdx.x*256+threadIdx.x;
    if(idx<2097152) out[15728640+idx]=g_h[idx];
    else if(idx<2125952) out[15728640+idx]=g_Tc[idx-2097152];
}

extern "C" void kernel_launch(void* const* d_in, const int* in_sizes, int n_in,
                              void* d_out, int out_size) {
    const float* x       =(const float*)d_in[0];
    const float* supports=(const float*)d_in[1];
    const float* conv1_w =(const float*)d_in[2];
    const float* conv1_b =(const float*)d_in[3];
    const float* tconv_w =(const float*)d_in[4];
    const float* tconv_b =(const float*)d_in[5];
    const float* s3_w1   =(const float*)d_in[6];
    const float* s3_w2   =(const float*)d_in[7];
    const float* s2_w1   =(const float*)d_in[8];
    const float* s2_w2   =(const float*)d_in[9];
    const float* wih     =(const float*)d_in[10];
    const float* whh     =(const float*)d_in[11];
    const float* bih     =(const float*)d_in[12];
    const float* bhh     =(const float*)d_in[13];
    const float* gcn_w   =(const float*)d_in[14];
    const float* gcn_b   =(const float*)d_in[15];
    const float* t_w1    =(const float*)d_in[16];
    const float* t_w2    =(const float*)d_in[17];
    const float* t_w     =(const float*)d_in[18];
    const float* t_b     =(const float*)d_in[19];
    const float* t_v     =(const float*)d_in[20];
    const float* t_bn_g  =(const float*)d_in[21];
    const float* t_bn_b  =(const float*)d_in[22];
    const float* ln_g    =(const float*)d_in[23];
    const float* ln_b    =(const float*)d_in[24];
    float* out=(float*)d_out;

    float *pG0,*pgb,*pP,*pxg,*pcv;
    __nv_bfloat16 *pSh,*pSl,*pwihh,*pwihl,*pwhhh,*pwhhl,*phh,*phl;
    __nv_bfloat16 *pa1h,*pa1l,*paTh,*paTl,*pchh,*pchl,*px1th,*px1tl,*pcolh,*pcoll,*pgwh,*pgwl;
    cudaGetSymbolAddress((void**)&pG0,  g_G0);
    cudaGetSymbolAddress((void**)&pgb,  g_gb);
    cudaGetSymbolAddress((void**)&pP,   g_P);
    cudaGetSymbolAddress((void**)&pxg,  g_xg);
    cudaGetSymbolAddress((void**)&pcv,  g_cv);
    cudaGetSymbolAddress((void**)&pSh,  g_Sh);
    cudaGetSymbolAddress((void**)&pSl,  g_Sl);
    cudaGetSymbolAddress((void**)&pwihh,g_wihh);
    cudaGetSymbolAddress((void**)&pwihl,g_wihl);
    cudaGetSymbolAddress((void**)&pwhhh,g_whhh);
    cudaGetSymbolAddress((void**)&pwhhl,g_whhl);
    cudaGetSymbolAddress((void**)&phh,  g_hh);
    cudaGetSymbolAddress((void**)&phl,  g_hl);
    cudaGetSymbolAddress((void**)&pa1h, g_a1h);
    cudaGetSymbolAddress((void**)&pa1l, g_a1l);
    cudaGetSymbolAddress((void**)&paTh, g_aTh);
    cudaGetSymbolAddress((void**)&paTl, g_aTl);
    cudaGetSymbolAddress((void**)&pchh, g_chh);
    cudaGetSymbolAddress((void**)&pchl, g_chl);
    cudaGetSymbolAddress((void**)&px1th,g_x1th);
    cudaGetSymbolAddress((void**)&px1tl,g_x1tl);
    cudaGetSymbolAddress((void**)&pcolh,g_colh);
    cudaGetSymbolAddress((void**)&pcoll,g_coll);
    cudaGetSymbolAddress((void**)&pgwh, g_gwh);
    cudaGetSymbolAddress((void**)&pgwl, g_gwl);

    cudaFuncSetAttribute(tgemm, cudaFuncAttributeMaxDynamicSharedMemorySize, 81920);
    const int TS = 81920;

    k_prep<<<8192,256>>>();
    k_wsplit<<<4096,256>>>(wih, whh, gcn_w, bih, bhh);
    k_conv1<<<4096,256>>>(x, conv1_w, conv1_b, tconv_w, tconv_b);
    k_x1t<<<dim3(512,8),256>>>();
    k_feat<<<4096,256>>>(s3_w1,s3_w2,s2_w1,s2_w2);
    k_slog<<<dim3(16,16,128),256>>>();
    tgemm<<<dim3(16,512,1),256,TS>>>(pSh,pSl,pwihh,pwihl,pG0,2048,512,0,0,0);
    for(int t=0;t<16;t++){
        tgemm<<<dim3(16,32,1),256,TS>>>(phh,phl,pwhhh,pwhhl,pgb,2048,512,0,0,0);
        k_cell<<<8192,256>>>(t);
    }
    k_adj1<<<8192,256>>>(supports);
    tgemm<<<dim3(4,4,8),256,TS>>>(pa1h,pa1l,paTh,paTl,pP,512,512,262144,262144,262144);
    k_cheb<<<8192,256>>>();
    tgemm<<<dim3(30,4,8),256,TS>>>(pa1h,pa1l,px1th,px1tl,pxg,        3840,512,262144,1966080,3932160);
    tgemm<<<dim3(30,4,8),256,TS>>>(pchh,pchl,px1th,px1tl,pxg+1966080,3840,512,262144,1966080,3932160);
    k_im2col<<<552960,256>>>();
    tgemm<<<dim3(240,1,8),256,TS>>>(pgwh,pgwl,pcolh,pcoll,pcv,30720,576,0,17694720,3932160);
    k_comb<<<61440,256>>>(gcn_b);
    k_tf1<<<4096,256>>>(t_w1);
    k_tf2<<<120,256>>>(t_w2);
    k_tatt<<<8,256>>>(t_w,t_b,t_v);
    k_bn1<<<1,64>>>(t_bn_g,t_bn_b);
    k_bn2<<<480,64>>>();
    k_x2<<<4096,256>>>();
    k_lnred<<<8,256>>>();
    k_lnout<<<61440,256>>>(ln_g,ln_b,out);
    if(out_size >= 17854592) k_tail<<<8306,256>>>(out);
}